// round 14
// baseline (speedup 1.0000x reference)
#include <cuda_runtime.h>
#include <cuda_fp16.h>
#include <math.h>
#include <cstdint>

// ---------------------------------------------------------------------------
// Problem constants
// ---------------------------------------------------------------------------
#define BB 4
#define TT 4096
#define NH 16
#define DH 64
#define HV 128
#define NDIM1 4128            // 2*KEY_DIM + VALUE_DIM + 2*N_HEADS
#define NDIM2 2048            // N_HEADS * HEAD_V
#define MM (BB*TT)            // 16384
#define KK 1024
#define N1PAD 4224            // 33 * 128 (W_in cols padded)
#define NTOT (N1PAD + NDIM2)  // 6272 combined weight cols

#define GM_SMEM 81920         // 2 buffers x (A 20480B + B 20480B), 160B rows

// ---------------------------------------------------------------------------
// Scratch (no cudaMalloc allowed)
// ---------------------------------------------------------------------------
__device__ float g_qkvba[(size_t)MM * NDIM1];
__device__ float g_gate [(size_t)MM * NDIM2];     // holds silu(gate) after GEMM
__device__ float g_q [(size_t)BB*NH*TT*DH];
__device__ float g_k [(size_t)BB*NH*TT*DH];
__device__ float g_v [(size_t)BB*NH*TT*HV];
__device__ float g_eg[(size_t)BB*NH*TT];
__device__ float g_be[(size_t)BB*NH*TT];
__device__ __half g_a16[(size_t)MM * KK];       // fp16, k-permuted A
__device__ __half g_wt16[(size_t)NTOT * KK];    // fp16, k-permuted W_in^T | W_gate^T

// ---------------------------------------------------------------------------
// Helpers
// ---------------------------------------------------------------------------
__device__ __forceinline__ uint32_t smem_u32(const void* p) {
    uint32_t a;
    asm("{ .reg .u64 t; cvta.to.shared.u64 t, %1; cvt.u32.u64 %0, t; }" : "=r"(a) : "l"(p));
    return a;
}
// fp16 k-permutation within each 16-group: one LDS.64 yields {2t,2t+1,2t+8,2t+9}
__device__ __forceinline__ int kperm16(int k) {
    return (k & ~15) | (((k & 7) >> 1) << 2) | (((k >> 3) & 1) << 1) | (k & 1);
}
__device__ __forceinline__ void cpa16(uint32_t dst, const void* src) {
    asm volatile("cp.async.cg.shared.global [%0], [%1], 16;" :: "r"(dst), "l"(src) : "memory");
}
__device__ __forceinline__ void cpa4(uint32_t dst, const void* src) {
    asm volatile("cp.async.ca.shared.global [%0], [%1], 4;" :: "r"(dst), "l"(src) : "memory");
}
__device__ __forceinline__ void cpa_commit() {
    asm volatile("cp.async.commit_group;" ::: "memory");
}
__device__ __forceinline__ void cpa_wait0() {
    asm volatile("cp.async.wait_group 0;" ::: "memory");
}

// fp16 mma m16n8k16, row.col, f32 accum (base ISA, sm_80+)
__device__ __forceinline__ void mma_f16(float* d, const uint32_t* a, const uint32_t* b) {
    asm volatile(
        "mma.sync.aligned.m16n8k16.row.col.f32.f16.f16.f32 "
        "{%0,%1,%2,%3}, {%4,%5,%6,%7}, {%8,%9}, {%0,%1,%2,%3};"
        : "+f"(d[0]), "+f"(d[1]), "+f"(d[2]), "+f"(d[3])
        : "r"(a[0]), "r"(a[1]), "r"(a[2]), "r"(a[3]), "r"(b[0]), "r"(b[1]));
}

// f32x2 packed math
typedef unsigned long long ull;
__device__ __forceinline__ ull fma2q(ull a, ull b, ull c) {
    ull d; asm("fma.rn.f32x2 %0, %1, %2, %3;" : "=l"(d) : "l"(a), "l"(b), "l"(c)); return d;
}
__device__ __forceinline__ ull mul2q(ull a, ull b) {
    ull d; asm("mul.rn.f32x2 %0, %1, %2;" : "=l"(d) : "l"(a), "l"(b)); return d;
}
__device__ __forceinline__ ull pack2q(float a, float b) {
    ull r; asm("mov.b64 %0, {%1, %2};" : "=l"(r) : "f"(a), "f"(b)); return r;
}
__device__ __forceinline__ float2 unpack2q(ull v) {
    float2 r; asm("mov.b64 {%0, %1}, %2;" : "=f"(r.x), "=f"(r.y) : "l"(v)); return r;
}
__device__ __forceinline__ float shfl_bfly(float v, int m) {
    float r;
    asm volatile("shfl.sync.bfly.b32 %0, %1, %2, 0x1f, 0xffffffff;" : "=f"(r) : "f"(v), "r"(m));
    return r;
}
__device__ __forceinline__ float silu_f(float y) { return y / (1.f + expf(-y)); }

// ---------------------------------------------------------------------------
// A pre-pass: fp16 convert + k-permute (pair granularity)
// ---------------------------------------------------------------------------
__global__ void __launch_bounds__(256) around16_kernel(const float* __restrict__ H) {
    size_t row = blockIdx.x;
    const float2* src = (const float2*)(H + row * KK);
    __half2* dst = (__half2*)(g_a16 + row * KK);
#pragma unroll
    for (int r = 0; r < 2; r++) {
        int p = threadIdx.x + r * 256;            // pair index 0..511
        int grp = p >> 3, q = p & 7;
        int pq = (q & 3) * 2 + (q >> 2);
        dst[grp * 8 + pq] = __float22half2_rn(src[p]);
    }
}

// ---------------------------------------------------------------------------
// Weight transpose: Wt16[n][kperm16(k)] = fp16(W[k][n]), zero-padded rows
// ---------------------------------------------------------------------------
__global__ void __launch_bounds__(256) transpose16_kernel(const float* __restrict__ W,
                                                          __half* __restrict__ Wt, int N) {
    __shared__ float tile[32][33];
    int k0 = blockIdx.x * 32, n0 = blockIdx.y * 32;
    int tx = threadIdx.x & 31, ty = threadIdx.x >> 5;   // 32 x 8
#pragma unroll
    for (int i = 0; i < 32; i += 8) {
        int n = n0 + tx;
        tile[ty + i][tx] = (n < N) ? W[(size_t)(k0 + ty + i) * N + n] : 0.f;
    }
    __syncthreads();
#pragma unroll
    for (int i = 0; i < 32; i += 8)
        Wt[(size_t)(n0 + ty + i) * KK + kperm16(k0 + tx)] = __float2half_rn(tile[tx][ty + i]);
}

// ---------------------------------------------------------------------------
// Fused fp16 mma.sync GEMM (cols [0,4128)->qkvba, [4224,6272)->silu->gate)
// CTA 128x128, 4 warps (2x2), warp tile 64x64, K-chunk 64, cp.async dbl buffer
// ---------------------------------------------------------------------------
__global__ void __launch_bounds__(128) gemm_mma(const __half* __restrict__ A,
                                                const __half* __restrict__ Bt,
                                                float* __restrict__ C1,
                                                float* __restrict__ C2) {
    extern __shared__ __half smh[];               // [2][A:128x80 | B:128x80]
    uint32_t sbase = smem_u32(smh);

    int tid = threadIdx.x;
    int lane = tid & 31, wid = tid >> 5;          // 4 warps
    int gid = lane >> 2, tig = lane & 3;
    int wm = wid & 1, wn = wid >> 1;              // 2 x 2 warp grid
    int m0 = blockIdx.y * 128;
    int n0 = blockIdx.x * 128;

    float acc[4][8][4];
#pragma unroll
    for (int mt = 0; mt < 4; mt++)
#pragma unroll
        for (int nt = 0; nt < 8; nt++)
#pragma unroll
            for (int i = 0; i < 4; i++) acc[mt][nt][i] = 0.f;

    const __half* aBase = A  + (size_t)m0 * KK;
    const __half* bBase = Bt + (size_t)n0 * KK;

    auto load_tile = [&](int ch, int b) {
        uint32_t a_dst = sbase + b * 40960u;
        uint32_t b_dst = a_dst + 20480u;
        const __half* aS = aBase + ch * 64;
        const __half* bS = bBase + ch * 64;
#pragma unroll
        for (int i = 0; i < 8; i++) {
            int id = tid + 128 * i;
            int row = id >> 3, seg = id & 7;
            cpa16(a_dst + row * 160u + seg * 16u, aS + (size_t)row * KK + seg * 8);
            cpa16(b_dst + row * 160u + seg * 16u, bS + (size_t)row * KK + seg * 8);
        }
        cpa_commit();
    };

    load_tile(0, 0);
    for (int ch = 0; ch < KK / 64; ch++) {
        if (ch + 1 < KK / 64) {
            load_tile(ch + 1, (ch + 1) & 1);
            asm volatile("cp.async.wait_group 1;" ::: "memory");
        } else {
            asm volatile("cp.async.wait_group 0;" ::: "memory");
        }
        __syncthreads();

        const __half* As_h = smh + (ch & 1) * 20480;   // halves
        const __half* Bs_h = As_h + 10240;
        const __half* aW = As_h + (wm * 64 + gid) * 80 + tig * 4;
        const __half* bW = Bs_h + (wn * 64 + gid) * 80 + tig * 4;

#pragma unroll
        for (int ks = 0; ks < 4; ks++) {
            uint32_t af[4][4];
#pragma unroll
            for (int mt = 0; mt < 4; mt++) {
                uint2 r0 = *(const uint2*)(aW + (mt * 16) * 80 + ks * 16);
                uint2 r1 = *(const uint2*)(aW + (mt * 16 + 8) * 80 + ks * 16);
                af[mt][0] = r0.x;
                af[mt][1] = r1.x;
                af[mt][2] = r0.y;
                af[mt][3] = r1.y;
            }
            uint32_t bf[8][2];
#pragma unroll
            for (int nt = 0; nt < 8; nt++) {
                uint2 v = *(const uint2*)(bW + (nt * 8) * 80 + ks * 16);
                bf[nt][0] = v.x;
                bf[nt][1] = v.y;
            }
#pragma unroll
            for (int mt = 0; mt < 4; mt++)
#pragma unroll
                for (int nt = 0; nt < 8; nt++)
                    mma_f16(acc[mt][nt], af[mt], bf[nt]);
        }
        __syncthreads();
    }

    // routed epilogue; gate columns get silu applied here (scan just multiplies)
#pragma unroll
    for (int mt = 0; mt < 4; mt++) {
        int row = m0 + wm * 64 + mt * 16 + gid;
#pragma unroll
        for (int nt = 0; nt < 8; nt++) {
            int col = n0 + wn * 64 + nt * 8 + 2 * tig;
            if (col < NDIM1) {
                *(float2*)&C1[(size_t)row * NDIM1 + col] =
                    make_float2(acc[mt][nt][0], acc[mt][nt][1]);
                *(float2*)&C1[(size_t)(row + 8) * NDIM1 + col] =
                    make_float2(acc[mt][nt][2], acc[mt][nt][3]);
            } else if (col >= N1PAD) {
                int c2 = col - N1PAD;
                *(float2*)&C2[(size_t)row * NDIM2 + c2] =
                    make_float2(silu_f(acc[mt][nt][0]), silu_f(acc[mt][nt][1]));
                *(float2*)&C2[(size_t)(row + 8) * NDIM2 + c2] =
                    make_float2(silu_f(acc[mt][nt][2]), silu_f(acc[mt][nt][3]));
            }
        }
    }
}

// ---------------------------------------------------------------------------
// Prep: causal conv4 + SiLU on q/k/v, l2norm on q/k, beta/exp(g).
// One block processes 4 consecutive t (same b): stencil taps hit L1 across
// iterations -> ~4x fewer DRAM reads of g_qkvba.
// ---------------------------------------------------------------------------
__global__ void __launch_bounds__(256) prep_kernel(const float* __restrict__ qw,
                                                   const float* __restrict__ kw,
                                                   const float* __restrict__ vw,
                                                   const float* __restrict__ dtb,
                                                   const float* __restrict__ Alog) {
    __shared__ float sq[1024];
    __shared__ float sk[1024];
    __shared__ float sscale[32];
    int row0 = blockIdx.x * 4;
    int b = row0 / TT;
    int tid = threadIdx.x;

    for (int it = 0; it < 4; it++) {
        int row = row0 + it;
        int t = row % TT;
        const float* base = g_qkvba + (size_t)row * NDIM1;

#pragma unroll
        for (int r = 0; r < 4; r++) {
            int c = tid + r * 256;
            float yq = 0.f, yk = 0.f;
#pragma unroll
            for (int i = 0; i < 4; i++) {
                int tt = t - 3 + i;
                if (tt >= 0) {
                    const float* xr = base + (size_t)(i - 3) * NDIM1;
                    yq = fmaf(xr[c], qw[c * 4 + i], yq);
                    yk = fmaf(xr[1024 + c], kw[c * 4 + i], yk);
                }
            }
            sq[c] = silu_f(yq);
            sk[c] = silu_f(yk);
        }
#pragma unroll
        for (int r = 0; r < 8; r++) {
            int cv = tid + r * 256;
            float yv = 0.f;
#pragma unroll
            for (int i = 0; i < 4; i++) {
                int tt = t - 3 + i;
                if (tt >= 0)
                    yv = fmaf(base[(size_t)(i - 3) * NDIM1 + 2048 + cv], vw[cv * 4 + i], yv);
            }
            int h = cv >> 7, j = cv & 127;
            g_v[(((size_t)(b * NH + h)) * TT + t) * HV + j] = silu_f(yv);
        }
        __syncthreads();
        if (tid < 16) {
            float s = 0.f;
#pragma unroll
            for (int d = 0; d < 64; d++) { float x = sq[tid * 64 + d]; s = fmaf(x, x, s); }
            sscale[tid] = rsqrtf(s + 1e-6f) * 0.125f;
        } else if (tid < 32) {
            int h = tid - 16;
            float s = 0.f;
#pragma unroll
            for (int d = 0; d < 64; d++) { float x = sk[h * 64 + d]; s = fmaf(x, x, s); }
            sscale[tid] = rsqrtf(s + 1e-6f);
        }
        if (tid < 16) {
            int h = tid;
            float bp = base[4096 + h];
            float ap = base[4112 + h];
            float beta = 1.f / (1.f + expf(-bp));
            float x = ap + dtb[h];
            float sp = (x > 20.f) ? x : log1pf(expf(x));
            float g = -expf(Alog[h]) * sp;
            size_t idx = (size_t)(b * NH + h) * TT + t;
            g_eg[idx] = expf(g);
            g_be[idx] = beta;
        }
        __syncthreads();
#pragma unroll
        for (int r = 0; r < 4; r++) {
            int c = tid + r * 256;
            int h = c >> 6, d = c & 63;
            size_t idx = (((size_t)(b * NH + h)) * TT + t) * DH + d;
            g_q[idx] = sq[c] * sscale[h];
            g_k[idx] = sk[c] * sscale[16 + h];
        }
        __syncthreads();
    }
}

// ---------------------------------------------------------------------------
// Scan: 128 blocks = (bh, column-half), 256 threads; 4 threads per V-column,
// each owning 16 of 64 d-values (8 f32x2 regs). 2-level shfl.bfly reduction.
// 8-step tiles, cp.async double buffered. Gate is pre-silu'd by the GEMM.
// ---------------------------------------------------------------------------
#define ST 8   // scan tile

__global__ void __launch_bounds__(256) scan_kernel(float* __restrict__ out) {
    __shared__ __align__(16) float sk[2][ST][64];
    __shared__ __align__(16) float sq[2][ST][64];
    __shared__ __align__(16) float sv[2][ST][64];
    __shared__ __align__(16) float sg[2][ST][64];
    __shared__ __align__(16) float seb[2][2][ST];   // [buf][0=eg,1=be][tt]

    int blk = blockIdx.x;            // 0..127
    int bh = blk >> 1, cf = blk & 1; // column-half
    int b = bh >> 4, h = bh & 15;
    int j = threadIdx.x;             // 0..255
    int col = j >> 2, sub = j & 3;   // col 0..63 within half, sub = d-quarter

    const float* kp  = g_k  + (size_t)bh * TT * DH;
    const float* qp  = g_q  + (size_t)bh * TT * DH;
    const float* vp0 = g_v  + (size_t)bh * TT * HV + cf * 64;
    const float* egp = g_eg + (size_t)bh * TT;
    const float* bep = g_be + (size_t)bh * TT;
    const float* gp0 = g_gate + (size_t)b * TT * NDIM2 + h * HV + cf * 64;
    float* op        = out    + (size_t)b * TT * NDIM2 + h * HV + cf * 64 + col;

    uint32_t a_sk = smem_u32(&sk[0][0][0]);
    uint32_t a_sq = smem_u32(&sq[0][0][0]);
    uint32_t a_sv = smem_u32(&sv[0][0][0]);
    uint32_t a_sg = smem_u32(&sg[0][0][0]);
    uint32_t a_se = smem_u32(&seb[0][0][0]);

    // k/v staged by threads 0-127, q/g by threads 128-255 (128 chunks each)
    auto issue_tile = [&](int t0, int buf) {
        int id = j & 127;
        int row = id >> 4, seg = id & 15;
        if (j < 128) {
            cpa16(a_sk + buf * (ST*64*4) + row * 256 + seg * 16,
                  kp + (size_t)(t0 + row) * DH + seg * 4);
            cpa16(a_sv + buf * (ST*64*4) + row * 256 + seg * 16,
                  vp0 + (size_t)(t0 + row) * HV + seg * 4);
        } else {
            cpa16(a_sq + buf * (ST*64*4) + row * 256 + seg * 16,
                  qp + (size_t)(t0 + row) * DH + seg * 4);
            cpa16(a_sg + buf * (ST*64*4) + row * 256 + seg * 16,
                  gp0 + (size_t)(t0 + row) * NDIM2 + seg * 4);
        }
        if (j < ST)            cpa4(a_se + buf * (2*ST*4) + j * 4,           egp + t0 + j);
        else if (j < 2 * ST)   cpa4(a_se + buf * (2*ST*4) + ST*4 + (j-ST)*4, bep + t0 + j - ST);
        cpa_commit();
    };

    ull S2[8];
#pragma unroll
    for (int d = 0; d < 8; d++) S2[d] = 0ULL;

    issue_tile(0, 0);
    cpa_wait0();
    __syncthreads();

    for (int t0 = 0; t0 < TT; t0 += ST) {
        int cur = (t0 >> 3) & 1;
        if (t0 + ST < TT) issue_tile(t0 + ST, cur ^ 1);

#pragma unroll 2
        for (int tt = 0; tt < ST; tt++) {
            float eg = seb[cur][0][tt], be = seb[cur][1][tt];
            float vcur = sv[cur][tt][col];
            float gcur = sg[cur][tt][col];       // already silu(gate)
            const ulonglong2* k2p = (const ulonglong2*)&sk[cur][tt][sub * 16];
            const ulonglong2* q2p = (const ulonglong2*)&sq[cur][tt][sub * 16];

            // partial kS over this thread's 16 d-values
            ull a0 = 0, a1 = 0, a2 = 0, a3 = 0;
#pragma unroll
            for (int i = 0; i < 2; i++) {
                ulonglong2 ka = k2p[i];
                ulonglong2 kb = k2p[i + 2];
                a0 = fma2q(ka.x, S2[2 * i],     a0);
                a1 = fma2q(ka.y, S2[2 * i + 1], a1);
                a2 = fma2q(kb.x, S2[2 * i + 4], a2);
                a3 = fma2q(kb.y, S2[2 * i + 5], a3);
            }
            float2 u0 = unpack2q(a0), u1 = unpack2q(a1), u2 = unpack2q(a2), u3 = unpack2q(a3);
            float kS = ((u0.x + u0.y) + (u1.x + u1.y)) + ((u2.x + u2.y) + (u3.x + u3.y));
            kS += shfl_bfly(kS, 1);
            kS += shfl_bfly(kS, 2);
            float vnew = (vcur - eg * kS) * be;

            ull eg2 = pack2q(eg, eg);
            ull vn2 = pack2q(vnew, vnew);
            ull o0 = 0, o1 = 0, o2 = 0, o3 = 0;
#pragma unroll
            for (int i = 0; i < 2; i++) {
                ulonglong2 ka = k2p[i],  kb = k2p[i + 2];
                ulonglong2 qa = q2p[i],  qb = q2p[i + 2];
                S2[2 * i]     = fma2q(ka.x, vn2, mul2q(S2[2 * i],     eg2)); o0 = fma2q(qa.x, S2[2 * i],     o0);
                S2[2 * i + 1] = fma2q(ka.y, vn2, mul2q(S2[2 * i + 1], eg2)); o1 = fma2q(qa.y, S2[2 * i + 1], o1);
                S2[2 * i + 4] = fma2q(kb.x, vn2, mul2q(S2[2 * i + 4], eg2)); o2 = fma2q(qb.x, S2[2 * i + 4], o2);
                S2[2 * i + 5] = fma2q(kb.y, vn2, mul2q(S2[2 * i + 5], eg2)); o3 = fma2q(qb.y, S2[2 * i + 5], o3);
            }
            float2 w0 = unpack2q(o0), w1 = unpack2q(o1), w2 = unpack2q(o2), w3 = unpack2q(o3);
            float o = ((w0.x + w0.y) + (w1.x + w1.y)) + ((w2.x + w2.y) + (w3.x + w3.y));
            o += shfl_bfly(o, 1);
            o += shfl_bfly(o, 2);

            if (sub == 0)
                op[(size_t)(t0 + tt) * NDIM2] = o * gcur;
        }

        if (t0 + ST < TT) cpa_wait0();
        __syncthreads();
    }
}

// ---------------------------------------------------------------------------
extern "C" void kernel_launch(void* const* d_in, const int* in_sizes, int n_in,
                              void* d_out, int out_size) {
    const float* H    = (const float*)d_in[0];
    const float* Win  = (const float*)d_in[1];
    const float* qw   = (const float*)d_in[2];
    const float* kw   = (const float*)d_in[3];
    const float* vw   = (const float*)d_in[4];
    const float* dtb  = (const float*)d_in[5];
    const float* Alog = (const float*)d_in[6];
    const float* Wg   = (const float*)d_in[7];
    float* out = (float*)d_out;

    void *p_wt = nullptr, *p_qkvba = nullptr, *p_gate = nullptr, *p_a = nullptr;
    cudaGetSymbolAddress(&p_wt,    g_wt16);
    cudaGetSymbolAddress(&p_qkvba, g_qkvba);
    cudaGetSymbolAddress(&p_gate,  g_gate);
    cudaGetSymbolAddress(&p_a,     g_a16);
    cudaFuncSetAttribute(gemm_mma, cudaFuncAttributeMaxDynamicSharedMemorySize, GM_SMEM);

    around16_kernel<<<MM, 256>>>(H);
    transpose16_kernel<<<dim3(KK / 32, N1PAD / 32), 256>>>(Win, (__half*)p_wt, NDIM1);
    transpose16_kernel<<<dim3(KK / 32, NDIM2 / 32), 256>>>(
        Wg, (__half*)p_wt + (size_t)N1PAD * KK, NDIM2);

    gemm_mma<<<dim3(NTOT / 128, MM / 128), 128, GM_SMEM>>>(
        (const __half*)p_a, (const __half*)p_wt, (float*)p_qkvba, (float*)p_gate);

    prep_kernel<<<MM / 4, 256>>>(qw, kw, vw, dtb, Alog);
    scan_kernel<<<2 * BB * NH, 256>>>(out);
}

// round 16
// speedup vs baseline: 1.2533x; 1.2533x over previous
#include <cuda_runtime.h>
#include <cuda_fp16.h>
#include <math.h>
#include <cstdint>

// ---------------------------------------------------------------------------
// Problem constants
// ---------------------------------------------------------------------------
#define BB 4
#define TT 4096
#define NH 16
#define DH 64
#define HV 128
#define NDIM1 4128            // 2*KEY_DIM + VALUE_DIM + 2*N_HEADS
#define NDIM2 2048            // N_HEADS * HEAD_V
#define MM (BB*TT)            // 16384
#define KK 1024
#define N1PAD 4352            // 34 * 128 (W_in cols padded so NTOT % 256 == 0)
#define NTOT (N1PAD + NDIM2)  // 6400 = 25 * 256 combined weight cols

#define GM_SMEM 122880        // 2 stages x (A 128x160B + B 256x160B)

// ---------------------------------------------------------------------------
// Scratch (no cudaMalloc allowed)
// ---------------------------------------------------------------------------
__device__ float g_qkvba[(size_t)MM * NDIM1];
__device__ float g_gate [(size_t)MM * NDIM2];     // holds silu(gate) after GEMM
__device__ float g_q [(size_t)BB*NH*TT*DH];
__device__ float g_k [(size_t)BB*NH*TT*DH];
__device__ float g_v [(size_t)BB*NH*TT*HV];
__device__ float g_eg[(size_t)BB*NH*TT];
__device__ float g_be[(size_t)BB*NH*TT];
__device__ __half g_a16[(size_t)MM * KK];       // fp16, k-permuted A
__device__ __half g_wt16[(size_t)NTOT * KK];    // fp16, k-permuted W_in^T | W_gate^T

// ---------------------------------------------------------------------------
// Helpers
// ---------------------------------------------------------------------------
__device__ __forceinline__ uint32_t smem_u32(const void* p) {
    uint32_t a;
    asm("{ .reg .u64 t; cvta.to.shared.u64 t, %1; cvt.u32.u64 %0, t; }" : "=r"(a) : "l"(p));
    return a;
}
// fp16 k-permutation within each 16-group: one LDS.64 yields {2t,2t+1,2t+8,2t+9}
__device__ __forceinline__ int kperm16(int k) {
    return (k & ~15) | (((k & 7) >> 1) << 2) | (((k >> 3) & 1) << 1) | (k & 1);
}
__device__ __forceinline__ void cpa16(uint32_t dst, const void* src) {
    asm volatile("cp.async.cg.shared.global [%0], [%1], 16;" :: "r"(dst), "l"(src) : "memory");
}
__device__ __forceinline__ void cpa4(uint32_t dst, const void* src) {
    asm volatile("cp.async.ca.shared.global [%0], [%1], 4;" :: "r"(dst), "l"(src) : "memory");
}
__device__ __forceinline__ void cpa_commit() {
    asm volatile("cp.async.commit_group;" ::: "memory");
}
__device__ __forceinline__ void cpa_wait0() {
    asm volatile("cp.async.wait_group 0;" ::: "memory");
}

// fp16 mma m16n8k16, row.col, f32 accum (base ISA, sm_80+)
__device__ __forceinline__ void mma_f16(float* d, const uint32_t* a, const uint32_t* b) {
    asm volatile(
        "mma.sync.aligned.m16n8k16.row.col.f32.f16.f16.f32 "
        "{%0,%1,%2,%3}, {%4,%5,%6,%7}, {%8,%9}, {%0,%1,%2,%3};"
        : "+f"(d[0]), "+f"(d[1]), "+f"(d[2]), "+f"(d[3])
        : "r"(a[0]), "r"(a[1]), "r"(a[2]), "r"(a[3]), "r"(b[0]), "r"(b[1]));
}

// f32x2 packed math
typedef unsigned long long ull;
__device__ __forceinline__ ull fma2q(ull a, ull b, ull c) {
    ull d; asm("fma.rn.f32x2 %0, %1, %2, %3;" : "=l"(d) : "l"(a), "l"(b), "l"(c)); return d;
}
__device__ __forceinline__ ull mul2q(ull a, ull b) {
    ull d; asm("mul.rn.f32x2 %0, %1, %2;" : "=l"(d) : "l"(a), "l"(b)); return d;
}
__device__ __forceinline__ ull pack2q(float a, float b) {
    ull r; asm("mov.b64 %0, {%1, %2};" : "=l"(r) : "f"(a), "f"(b)); return r;
}
__device__ __forceinline__ float2 unpack2q(ull v) {
    float2 r; asm("mov.b64 {%0, %1}, %2;" : "=f"(r.x), "=f"(r.y) : "l"(v)); return r;
}
__device__ __forceinline__ float shfl_bfly1(float v) {
    float r;
    asm volatile("shfl.sync.bfly.b32 %0, %1, 1, 0x1f, 0xffffffff;" : "=f"(r) : "f"(v));
    return r;
}
__device__ __forceinline__ float silu_f(float y) { return y / (1.f + expf(-y)); }

// ---------------------------------------------------------------------------
// A pre-pass: fp16 convert + k-permute (pair granularity)
// ---------------------------------------------------------------------------
__global__ void __launch_bounds__(256) around16_kernel(const float* __restrict__ H) {
    size_t row = blockIdx.x;
    const float2* src = (const float2*)(H + row * KK);
    __half2* dst = (__half2*)(g_a16 + row * KK);
#pragma unroll
    for (int r = 0; r < 2; r++) {
        int p = threadIdx.x + r * 256;            // pair index 0..511
        int grp = p >> 3, q = p & 7;
        int pq = (q & 3) * 2 + (q >> 2);
        dst[grp * 8 + pq] = __float22half2_rn(src[p]);
    }
}

// ---------------------------------------------------------------------------
// Weight transpose: Wt16[n][kperm16(k)] = fp16(W[k][n]), zero-padded rows
// ---------------------------------------------------------------------------
__global__ void __launch_bounds__(256) transpose16_kernel(const float* __restrict__ W,
                                                          __half* __restrict__ Wt, int N) {
    __shared__ float tile[32][33];
    int k0 = blockIdx.x * 32, n0 = blockIdx.y * 32;
    int tx = threadIdx.x & 31, ty = threadIdx.x >> 5;   // 32 x 8
#pragma unroll
    for (int i = 0; i < 32; i += 8) {
        int n = n0 + tx;
        tile[ty + i][tx] = (n < N) ? W[(size_t)(k0 + ty + i) * N + n] : 0.f;
    }
    __syncthreads();
#pragma unroll
    for (int i = 0; i < 32; i += 8)
        Wt[(size_t)(n0 + ty + i) * KK + kperm16(k0 + tx)] = __float2half_rn(tile[tx][ty + i]);
}

// ---------------------------------------------------------------------------
// Fused fp16 mma.sync GEMM (cols [0,4128)->qkvba, [4352,6400)->silu->gate)
// CTA 128x256, 8 warps (2 M x 4 N), warp tile 64x64, K-chunk 64,
// cp.async double buffer. Smem rows 160B: conflict-free LDS.64 fragments.
// ---------------------------------------------------------------------------
__global__ void __launch_bounds__(256) gemm_mma(const __half* __restrict__ A,
                                                const __half* __restrict__ Bt,
                                                float* __restrict__ C1,
                                                float* __restrict__ C2) {
    extern __shared__ __half smh[];               // [2][A:128x80 | B:256x80] halves
    uint32_t sbase = smem_u32(smh);

    int tid = threadIdx.x;
    int lane = tid & 31, wid = tid >> 5;          // 8 warps
    int gid = lane >> 2, tig = lane & 3;
    int wm = wid & 1, wn = wid >> 1;              // 2 x 4 warp grid
    int m0 = blockIdx.y * 128;
    int n0 = blockIdx.x * 256;

    float acc[4][8][4];
#pragma unroll
    for (int mt = 0; mt < 4; mt++)
#pragma unroll
        for (int nt = 0; nt < 8; nt++)
#pragma unroll
            for (int i = 0; i < 4; i++) acc[mt][nt][i] = 0.f;

    const __half* aBase = A  + (size_t)m0 * KK;
    const __half* bBase = Bt + (size_t)n0 * KK;

    // stage K-chunk of 64 halves (128B per row): A 1024 chunks + B 2048 chunks
    auto load_tile = [&](int ch, int b) {
        uint32_t a_dst = sbase + b * 61440u;
        uint32_t b_dst = a_dst + 20480u;
        const __half* aS = aBase + ch * 64;
        const __half* bS = bBase + ch * 64;
#pragma unroll
        for (int i = 0; i < 12; i++) {
            int id = tid + 256 * i;
            if (id < 1024) {
                int row = id >> 3, seg = id & 7;
                cpa16(a_dst + row * 160u + seg * 16u, aS + (size_t)row * KK + seg * 8);
            } else {
                int id2 = id - 1024;
                int row = id2 >> 3, seg = id2 & 7;
                cpa16(b_dst + row * 160u + seg * 16u, bS + (size_t)row * KK + seg * 8);
            }
        }
        cpa_commit();
    };

    load_tile(0, 0);
    for (int ch = 0; ch < KK / 64; ch++) {
        if (ch + 1 < KK / 64) {
            load_tile(ch + 1, (ch + 1) & 1);
            asm volatile("cp.async.wait_group 1;" ::: "memory");
        } else {
            asm volatile("cp.async.wait_group 0;" ::: "memory");
        }
        __syncthreads();

        const __half* As_h = smh + (ch & 1) * 30720;   // halves
        const __half* Bs_h = As_h + 10240;
        const __half* aW = As_h + (wm * 64 + gid) * 80 + tig * 4;
        const __half* bW = Bs_h + (wn * 64 + gid) * 80 + tig * 4;

#pragma unroll
        for (int ks = 0; ks < 4; ks++) {
            uint32_t af[4][4];
#pragma unroll
            for (int mt = 0; mt < 4; mt++) {
                uint2 r0 = *(const uint2*)(aW + (mt * 16) * 80 + ks * 16);
                uint2 r1 = *(const uint2*)(aW + (mt * 16 + 8) * 80 + ks * 16);
                af[mt][0] = r0.x;
                af[mt][1] = r1.x;
                af[mt][2] = r0.y;
                af[mt][3] = r1.y;
            }
            uint32_t bf[8][2];
#pragma unroll
            for (int nt = 0; nt < 8; nt++) {
                uint2 v = *(const uint2*)(bW + (nt * 8) * 80 + ks * 16);
                bf[nt][0] = v.x;
                bf[nt][1] = v.y;
            }
#pragma unroll
            for (int mt = 0; mt < 4; mt++)
#pragma unroll
                for (int nt = 0; nt < 8; nt++)
                    mma_f16(acc[mt][nt], af[mt], bf[nt]);
        }
        __syncthreads();
    }

    // routed epilogue; gate columns get silu applied here (scan just multiplies)
#pragma unroll
    for (int mt = 0; mt < 4; mt++) {
        int row = m0 + wm * 64 + mt * 16 + gid;
#pragma unroll
        for (int nt = 0; nt < 8; nt++) {
            int col = n0 + wn * 64 + nt * 8 + 2 * tig;
            if (col < NDIM1) {
                *(float2*)&C1[(size_t)row * NDIM1 + col] =
                    make_float2(acc[mt][nt][0], acc[mt][nt][1]);
                *(float2*)&C1[(size_t)(row + 8) * NDIM1 + col] =
                    make_float2(acc[mt][nt][2], acc[mt][nt][3]);
            } else if (col >= N1PAD) {
                int c2 = col - N1PAD;
                *(float2*)&C2[(size_t)row * NDIM2 + c2] =
                    make_float2(silu_f(acc[mt][nt][0]), silu_f(acc[mt][nt][1]));
                *(float2*)&C2[(size_t)(row + 8) * NDIM2 + c2] =
                    make_float2(silu_f(acc[mt][nt][2]), silu_f(acc[mt][nt][3]));
            }
        }
    }
}

// ---------------------------------------------------------------------------
// Prep: causal conv4 + SiLU on q/k/v, l2norm on q/k, beta/exp(g)  (R12 form)
// ---------------------------------------------------------------------------
__global__ void __launch_bounds__(256) prep_kernel(const float* __restrict__ qw,
                                                   const float* __restrict__ kw,
                                                   const float* __restrict__ vw,
                                                   const float* __restrict__ dtb,
                                                   const float* __restrict__ Alog) {
    __shared__ float sq[1024];
    __shared__ float sk[1024];
    __shared__ float sscale[32];
    int row = blockIdx.x;
    int b = row / TT, t = row % TT;
    int tid = threadIdx.x;
    const float* base = g_qkvba + (size_t)row * NDIM1;

#pragma unroll
    for (int r = 0; r < 4; r++) {
        int c = tid + r * 256;
        float yq = 0.f, yk = 0.f;
#pragma unroll
        for (int i = 0; i < 4; i++) {
            int tt = t - 3 + i;
            if (tt >= 0) {
                const float* xr = base + (size_t)(i - 3) * NDIM1;
                yq = fmaf(xr[c], qw[c * 4 + i], yq);
                yk = fmaf(xr[1024 + c], kw[c * 4 + i], yk);
            }
        }
        sq[c] = silu_f(yq);
        sk[c] = silu_f(yk);
    }
#pragma unroll
    for (int r = 0; r < 8; r++) {
        int cv = tid + r * 256;
        float yv = 0.f;
#pragma unroll
        for (int i = 0; i < 4; i++) {
            int tt = t - 3 + i;
            if (tt >= 0)
                yv = fmaf(base[(size_t)(i - 3) * NDIM1 + 2048 + cv], vw[cv * 4 + i], yv);
        }
        int h = cv >> 7, j = cv & 127;
        g_v[(((size_t)(b * NH + h)) * TT + t) * HV + j] = silu_f(yv);
    }
    __syncthreads();
    if (tid < 16) {
        float s = 0.f;
#pragma unroll
        for (int d = 0; d < 64; d++) { float x = sq[tid * 64 + d]; s = fmaf(x, x, s); }
        sscale[tid] = rsqrtf(s + 1e-6f) * 0.125f;
    } else if (tid < 32) {
        int h = tid - 16;
        float s = 0.f;
#pragma unroll
        for (int d = 0; d < 64; d++) { float x = sk[h * 64 + d]; s = fmaf(x, x, s); }
        sscale[tid] = rsqrtf(s + 1e-6f);
    }
    if (tid < 16) {
        int h = tid;
        float bp = base[4096 + h];
        float ap = base[4112 + h];
        float beta = 1.f / (1.f + expf(-bp));
        float x = ap + dtb[h];
        float sp = (x > 20.f) ? x : log1pf(expf(x));
        float g = -expf(Alog[h]) * sp;
        size_t idx = (size_t)(b * NH + h) * TT + t;
        g_eg[idx] = expf(g);
        g_be[idx] = beta;
    }
    __syncthreads();
#pragma unroll
    for (int r = 0; r < 4; r++) {
        int c = tid + r * 256;
        int h = c >> 6, d = c & 63;
        size_t idx = (((size_t)(b * NH + h)) * TT + t) * DH + d;
        g_q[idx] = sq[c] * sscale[h];
        g_k[idx] = sk[c] * sscale[16 + h];
    }
}

// ---------------------------------------------------------------------------
// Scan (R12 form): 128 blocks = (bh, column-half), 128 threads; 2 threads per
// V-column, each owning 32 of 64 d-values. One shfl.bfly(1) per reduction.
// 8-step tiles, cp.async double buffered. Gate is pre-silu'd by the GEMM.
// ---------------------------------------------------------------------------
#define ST 8   // scan tile

__global__ void __launch_bounds__(128) scan_kernel(float* __restrict__ out) {
    __shared__ __align__(16) float sk[2][ST][64];
    __shared__ __align__(16) float sq[2][ST][64];
    __shared__ __align__(16) float sv[2][ST][64];
    __shared__ __align__(16) float sg[2][ST][64];
    __shared__ __align__(16) float seb[2][2][ST];   // [buf][0=eg,1=be][tt]

    int blk = blockIdx.x;            // 0..127
    int bh = blk >> 1, cf = blk & 1; // column-half
    int b = bh >> 4, h = bh & 15;
    int j = threadIdx.x;
    int col = j >> 1, sub = j & 1;   // col 0..63 within half, sub = d-half

    const float* kp  = g_k  + (size_t)bh * TT * DH;
    const float* qp  = g_q  + (size_t)bh * TT * DH;
    const float* vp0 = g_v  + (size_t)bh * TT * HV + cf * 64;
    const float* egp = g_eg + (size_t)bh * TT;
    const float* bep = g_be + (size_t)bh * TT;
    const float* gp0 = g_gate + (size_t)b * TT * NDIM2 + h * HV + cf * 64;
    float* op        = out    + (size_t)b * TT * NDIM2 + h * HV + cf * 64 + col;

    uint32_t a_sk = smem_u32(&sk[0][0][0]);
    uint32_t a_sq = smem_u32(&sq[0][0][0]);
    uint32_t a_sv = smem_u32(&sv[0][0][0]);
    uint32_t a_sg = smem_u32(&sg[0][0][0]);
    uint32_t a_se = smem_u32(&seb[0][0][0]);

    auto issue_tile = [&](int t0, int buf) {
        int row = j >> 4, seg = j & 15;
        cpa16(a_sk + buf * (ST*64*4) + row * 256 + seg * 16,
              kp + (size_t)(t0 + row) * DH + seg * 4);
        cpa16(a_sq + buf * (ST*64*4) + row * 256 + seg * 16,
              qp + (size_t)(t0 + row) * DH + seg * 4);
        cpa16(a_sv + buf * (ST*64*4) + row * 256 + seg * 16,
              vp0 + (size_t)(t0 + row) * HV + seg * 4);
        cpa16(a_sg + buf * (ST*64*4) + row * 256 + seg * 16,
              gp0 + (size_t)(t0 + row) * NDIM2 + seg * 4);
        if (j < ST)            cpa4(a_se + buf * (2*ST*4) + j * 4,           egp + t0 + j);
        else if (j < 2 * ST)   cpa4(a_se + buf * (2*ST*4) + ST*4 + (j-ST)*4, bep + t0 + j - ST);
        cpa_commit();
    };

    ull S2[16];
#pragma unroll
    for (int d = 0; d < 16; d++) S2[d] = 0ULL;

    issue_tile(0, 0);
    cpa_wait0();
    __syncthreads();

    for (int t0 = 0; t0 < TT; t0 += ST) {
        int cur = (t0 >> 3) & 1;
        if (t0 + ST < TT) issue_tile(t0 + ST, cur ^ 1);

#pragma unroll 2
        for (int tt = 0; tt < ST; tt++) {
            float eg = seb[cur][0][tt], be = seb[cur][1][tt];
            float vcur = sv[cur][tt][col];
            float gcur = sg[cur][tt][col];       // already silu(gate)
            const ulonglong2* k2p = (const ulonglong2*)&sk[cur][tt][sub * 32];
            const ulonglong2* q2p = (const ulonglong2*)&sq[cur][tt][sub * 32];

            ull a0 = 0, a1 = 0, a2 = 0, a3 = 0;
#pragma unroll
            for (int i = 0; i < 4; i++) {
                ulonglong2 ka = k2p[i];
                ulonglong2 kb = k2p[i + 4];
                a0 = fma2q(ka.x, S2[2 * i],     a0);
                a1 = fma2q(ka.y, S2[2 * i + 1], a1);
                a2 = fma2q(kb.x, S2[2 * i + 8], a2);
                a3 = fma2q(kb.y, S2[2 * i + 9], a3);
            }
            float2 u0 = unpack2q(a0), u1 = unpack2q(a1), u2 = unpack2q(a2), u3 = unpack2q(a3);
            float kS_part = ((u0.x + u0.y) + (u1.x + u1.y)) + ((u2.x + u2.y) + (u3.x + u3.y));
            float kS = kS_part + shfl_bfly1(kS_part);
            float vnew = (vcur - eg * kS) * be;

            ull eg2 = pack2q(eg, eg);
            ull vn2 = pack2q(vnew, vnew);
            ull o0 = 0, o1 = 0, o2 = 0, o3 = 0;
#pragma unroll
            for (int i = 0; i < 4; i++) {
                ulonglong2 ka = k2p[i],  kb = k2p[i + 4];
                ulonglong2 qa = q2p[i],  qb = q2p[i + 4];
                S2[2 * i]     = fma2q(ka.x, vn2, mul2q(S2[2 * i],     eg2)); o0 = fma2q(qa.x, S2[2 * i],     o0);
                S2[2 * i + 1] = fma2q(ka.y, vn2, mul2q(S2[2 * i + 1], eg2)); o1 = fma2q(qa.y, S2[2 * i + 1], o1);
                S2[2 * i + 8] = fma2q(kb.x, vn2, mul2q(S2[2 * i + 8], eg2)); o2 = fma2q(qb.x, S2[2 * i + 8], o2);
                S2[2 * i + 9] = fma2q(kb.y, vn2, mul2q(S2[2 * i + 9], eg2)); o3 = fma2q(qb.y, S2[2 * i + 9], o3);
            }
            float2 w0 = unpack2q(o0), w1 = unpack2q(o1), w2 = unpack2q(o2), w3 = unpack2q(o3);
            float o_part = ((w0.x + w0.y) + (w1.x + w1.y)) + ((w2.x + w2.y) + (w3.x + w3.y));
            float o = o_part + shfl_bfly1(o_part);

            if (sub == 0)
                op[(size_t)(t0 + tt) * NDIM2] = o * gcur;
        }

        if (t0 + ST < TT) cpa_wait0();
        __syncthreads();
    }
}

// ---------------------------------------------------------------------------
extern "C" void kernel_launch(void* const* d_in, const int* in_sizes, int n_in,
                              void* d_out, int out_size) {
    const float* H    = (const float*)d_in[0];
    const float* Win  = (const float*)d_in[1];
    const float* qw   = (const float*)d_in[2];
    const float* kw   = (const float*)d_in[3];
    const float* vw   = (const float*)d_in[4];
    const float* dtb  = (const float*)d_in[5];
    const float* Alog = (const float*)d_in[6];
    const float* Wg   = (const float*)d_in[7];
    float* out = (float*)d_out;

    void *p_wt = nullptr, *p_qkvba = nullptr, *p_gate = nullptr, *p_a = nullptr;
    cudaGetSymbolAddress(&p_wt,    g_wt16);
    cudaGetSymbolAddress(&p_qkvba, g_qkvba);
    cudaGetSymbolAddress(&p_gate,  g_gate);
    cudaGetSymbolAddress(&p_a,     g_a16);
    cudaFuncSetAttribute(gemm_mma, cudaFuncAttributeMaxDynamicSharedMemorySize, GM_SMEM);

    around16_kernel<<<MM, 256>>>(H);
    transpose16_kernel<<<dim3(KK / 32, N1PAD / 32), 256>>>(Win, (__half*)p_wt, NDIM1);
    transpose16_kernel<<<dim3(KK / 32, NDIM2 / 32), 256>>>(
        Wg, (__half*)p_wt + (size_t)N1PAD * KK, NDIM2);

    gemm_mma<<<dim3(NTOT / 256, MM / 128), 256, GM_SMEM>>>(
        (const __half*)p_a, (const __half*)p_wt, (float*)p_qkvba, (float*)p_gate);

    prep_kernel<<<MM, 256>>>(qw, kw, vw, dtb, Alog);
    scan_kernel<<<2 * BB * NH, 128>>>(out);
}

// round 17
// speedup vs baseline: 1.3753x; 1.0973x over previous
#include <cuda_runtime.h>
#include <cuda_fp16.h>
#include <math.h>
#include <cstdint>

// ---------------------------------------------------------------------------
// Problem constants
// ---------------------------------------------------------------------------
#define BB 4
#define TT 4096
#define NH 16
#define DH 64
#define HV 128
#define NDIM1 4128            // 2*KEY_DIM + VALUE_DIM + 2*N_HEADS
#define NDIM2 2048            // N_HEADS * HEAD_V
#define MM (BB*TT)            // 16384
#define KK 1024
#define N1PAD 4224            // 33 * 128 (W_in cols padded)
#define NTOT (N1PAD + NDIM2)  // 6272 combined weight cols

#define GM_SMEM 81920         // 2 buffers x (A 20480B + B 20480B), 160B rows

// ---------------------------------------------------------------------------
// Scratch (no cudaMalloc allowed)
// ---------------------------------------------------------------------------
__device__ float g_qkvba[(size_t)MM * NDIM1];
__device__ float g_gate [(size_t)MM * NDIM2];     // holds silu(gate) after GEMM
__device__ float g_q [(size_t)BB*NH*TT*DH];
__device__ float g_k [(size_t)BB*NH*TT*DH];
__device__ float g_v [(size_t)BB*NH*TT*HV];
__device__ float g_eg[(size_t)BB*NH*TT];
__device__ float g_be[(size_t)BB*NH*TT];
__device__ __half g_a16[(size_t)MM * KK];       // fp16, k-permuted A
__device__ __half g_wt16[(size_t)NTOT * KK];    // fp16, k-permuted W_in^T | W_gate^T

// ---------------------------------------------------------------------------
// Helpers
// ---------------------------------------------------------------------------
__device__ __forceinline__ uint32_t smem_u32(const void* p) {
    uint32_t a;
    asm("{ .reg .u64 t; cvta.to.shared.u64 t, %1; cvt.u32.u64 %0, t; }" : "=r"(a) : "l"(p));
    return a;
}
// fp16 k-permutation within each 16-group: one LDS.64 yields {2t,2t+1,2t+8,2t+9}
__device__ __forceinline__ int kperm16(int k) {
    return (k & ~15) | (((k & 7) >> 1) << 2) | (((k >> 3) & 1) << 1) | (k & 1);
}
__device__ __forceinline__ void cpa16(uint32_t dst, const void* src) {
    asm volatile("cp.async.cg.shared.global [%0], [%1], 16;" :: "r"(dst), "l"(src) : "memory");
}
__device__ __forceinline__ void cpa4(uint32_t dst, const void* src) {
    asm volatile("cp.async.ca.shared.global [%0], [%1], 4;" :: "r"(dst), "l"(src) : "memory");
}
__device__ __forceinline__ void cpa_commit() {
    asm volatile("cp.async.commit_group;" ::: "memory");
}
__device__ __forceinline__ void cpa_wait0() {
    asm volatile("cp.async.wait_group 0;" ::: "memory");
}

// fp16 mma m16n8k16, row.col, f32 accum (base ISA, sm_80+)
__device__ __forceinline__ void mma_f16(float* d, const uint32_t* a, const uint32_t* b) {
    asm volatile(
        "mma.sync.aligned.m16n8k16.row.col.f32.f16.f16.f32 "
        "{%0,%1,%2,%3}, {%4,%5,%6,%7}, {%8,%9}, {%0,%1,%2,%3};"
        : "+f"(d[0]), "+f"(d[1]), "+f"(d[2]), "+f"(d[3])
        : "r"(a[0]), "r"(a[1]), "r"(a[2]), "r"(a[3]), "r"(b[0]), "r"(b[1]));
}

// f32x2 packed math
typedef unsigned long long ull;
__device__ __forceinline__ ull fma2q(ull a, ull b, ull c) {
    ull d; asm("fma.rn.f32x2 %0, %1, %2, %3;" : "=l"(d) : "l"(a), "l"(b), "l"(c)); return d;
}
__device__ __forceinline__ ull mul2q(ull a, ull b) {
    ull d; asm("mul.rn.f32x2 %0, %1, %2;" : "=l"(d) : "l"(a), "l"(b)); return d;
}
__device__ __forceinline__ ull pack2q(float a, float b) {
    ull r; asm("mov.b64 %0, {%1, %2};" : "=l"(r) : "f"(a), "f"(b)); return r;
}
__device__ __forceinline__ float2 unpack2q(ull v) {
    float2 r; asm("mov.b64 {%0, %1}, %2;" : "=f"(r.x), "=f"(r.y) : "l"(v)); return r;
}
__device__ __forceinline__ float shfl_bfly1(float v) {
    float r;
    asm volatile("shfl.sync.bfly.b32 %0, %1, 1, 0x1f, 0xffffffff;" : "=f"(r) : "f"(v));
    return r;
}
__device__ __forceinline__ float silu_f(float y) { return y / (1.f + expf(-y)); }
__device__ __forceinline__ float4 silu4(float4 y) {
    return make_float4(silu_f(y.x), silu_f(y.y), silu_f(y.z), silu_f(y.w));
}
__device__ __forceinline__ float wsel(float4 w, int i) {
    return (i == 0) ? w.x : (i == 1) ? w.y : (i == 2) ? w.z : w.w;
}

// ---------------------------------------------------------------------------
// A pre-pass: fp16 convert + k-permute (pair granularity)
// ---------------------------------------------------------------------------
__global__ void __launch_bounds__(256) around16_kernel(const float* __restrict__ H) {
    size_t row = blockIdx.x;
    const float2* src = (const float2*)(H + row * KK);
    __half2* dst = (__half2*)(g_a16 + row * KK);
#pragma unroll
    for (int r = 0; r < 2; r++) {
        int p = threadIdx.x + r * 256;            // pair index 0..511
        int grp = p >> 3, q = p & 7;
        int pq = (q & 3) * 2 + (q >> 2);
        dst[grp * 8 + pq] = __float22half2_rn(src[p]);
    }
}

// ---------------------------------------------------------------------------
// Weight transpose: Wt16[n][kperm16(k)] = fp16(W[k][n]), zero-padded rows
// ---------------------------------------------------------------------------
__global__ void __launch_bounds__(256) transpose16_kernel(const float* __restrict__ W,
                                                          __half* __restrict__ Wt, int N) {
    __shared__ float tile[32][33];
    int k0 = blockIdx.x * 32, n0 = blockIdx.y * 32;
    int tx = threadIdx.x & 31, ty = threadIdx.x >> 5;   // 32 x 8
#pragma unroll
    for (int i = 0; i < 32; i += 8) {
        int n = n0 + tx;
        tile[ty + i][tx] = (n < N) ? W[(size_t)(k0 + ty + i) * N + n] : 0.f;
    }
    __syncthreads();
#pragma unroll
    for (int i = 0; i < 32; i += 8)
        Wt[(size_t)(n0 + ty + i) * KK + kperm16(k0 + tx)] = __float2half_rn(tile[tx][ty + i]);
}

// ---------------------------------------------------------------------------
// Fused fp16 mma.sync GEMM (cols [0,4128)->qkvba, [4224,6272)->silu->gate)
// CTA 128x128, 4 warps (2x2), warp tile 64x64, K-chunk 64, cp.async dbl buffer
// (R12 configuration — 2 CTAs/SM interleave across barriers)
// ---------------------------------------------------------------------------
__global__ void __launch_bounds__(128) gemm_mma(const __half* __restrict__ A,
                                                const __half* __restrict__ Bt,
                                                float* __restrict__ C1,
                                                float* __restrict__ C2) {
    extern __shared__ __half smh[];               // [2][A:128x80 | B:128x80]
    uint32_t sbase = smem_u32(smh);

    int tid = threadIdx.x;
    int lane = tid & 31, wid = tid >> 5;          // 4 warps
    int gid = lane >> 2, tig = lane & 3;
    int wm = wid & 1, wn = wid >> 1;              // 2 x 2 warp grid
    int m0 = blockIdx.y * 128;
    int n0 = blockIdx.x * 128;

    float acc[4][8][4];
#pragma unroll
    for (int mt = 0; mt < 4; mt++)
#pragma unroll
        for (int nt = 0; nt < 8; nt++)
#pragma unroll
            for (int i = 0; i < 4; i++) acc[mt][nt][i] = 0.f;

    const __half* aBase = A  + (size_t)m0 * KK;
    const __half* bBase = Bt + (size_t)n0 * KK;

    auto load_tile = [&](int ch, int b) {
        uint32_t a_dst = sbase + b * 40960u;
        uint32_t b_dst = a_dst + 20480u;
        const __half* aS = aBase + ch * 64;
        const __half* bS = bBase + ch * 64;
#pragma unroll
        for (int i = 0; i < 8; i++) {
            int id = tid + 128 * i;
            int row = id >> 3, seg = id & 7;
            cpa16(a_dst + row * 160u + seg * 16u, aS + (size_t)row * KK + seg * 8);
            cpa16(b_dst + row * 160u + seg * 16u, bS + (size_t)row * KK + seg * 8);
        }
        cpa_commit();
    };

    load_tile(0, 0);
    for (int ch = 0; ch < KK / 64; ch++) {
        if (ch + 1 < KK / 64) {
            load_tile(ch + 1, (ch + 1) & 1);
            asm volatile("cp.async.wait_group 1;" ::: "memory");
        } else {
            asm volatile("cp.async.wait_group 0;" ::: "memory");
        }
        __syncthreads();

        const __half* As_h = smh + (ch & 1) * 20480;   // halves
        const __half* Bs_h = As_h + 10240;
        const __half* aW = As_h + (wm * 64 + gid) * 80 + tig * 4;
        const __half* bW = Bs_h + (wn * 64 + gid) * 80 + tig * 4;

#pragma unroll
        for (int ks = 0; ks < 4; ks++) {
            uint32_t af[4][4];
#pragma unroll
            for (int mt = 0; mt < 4; mt++) {
                uint2 r0 = *(const uint2*)(aW + (mt * 16) * 80 + ks * 16);
                uint2 r1 = *(const uint2*)(aW + (mt * 16 + 8) * 80 + ks * 16);
                af[mt][0] = r0.x;
                af[mt][1] = r1.x;
                af[mt][2] = r0.y;
                af[mt][3] = r1.y;
            }
            uint32_t bf[8][2];
#pragma unroll
            for (int nt = 0; nt < 8; nt++) {
                uint2 v = *(const uint2*)(bW + (nt * 8) * 80 + ks * 16);
                bf[nt][0] = v.x;
                bf[nt][1] = v.y;
            }
#pragma unroll
            for (int mt = 0; mt < 4; mt++)
#pragma unroll
                for (int nt = 0; nt < 8; nt++)
                    mma_f16(acc[mt][nt], af[mt], bf[nt]);
        }
        __syncthreads();
    }

    // routed epilogue; gate columns get silu applied here (scan just multiplies)
#pragma unroll
    for (int mt = 0; mt < 4; mt++) {
        int row = m0 + wm * 64 + mt * 16 + gid;
#pragma unroll
        for (int nt = 0; nt < 8; nt++) {
            int col = n0 + wn * 64 + nt * 8 + 2 * tig;
            if (col < NDIM1) {
                *(float2*)&C1[(size_t)row * NDIM1 + col] =
                    make_float2(acc[mt][nt][0], acc[mt][nt][1]);
                *(float2*)&C1[(size_t)(row + 8) * NDIM1 + col] =
                    make_float2(acc[mt][nt][2], acc[mt][nt][3]);
            } else if (col >= N1PAD) {
                int c2 = col - N1PAD;
                *(float2*)&C2[(size_t)row * NDIM2 + c2] =
                    make_float2(silu_f(acc[mt][nt][0]), silu_f(acc[mt][nt][1]));
                *(float2*)&C2[(size_t)(row + 8) * NDIM2 + c2] =
                    make_float2(silu_f(acc[mt][nt][2]), silu_f(acc[mt][nt][3]));
            }
        }
    }
}

// ---------------------------------------------------------------------------
// Prep: causal conv4 + SiLU on q/k/v, l2norm on q/k, beta/exp(g).
// Vectorized: 256 threads, float4 loads/stores everywhere.
// ---------------------------------------------------------------------------
__global__ void __launch_bounds__(256) prep_kernel(const float* __restrict__ qw,
                                                   const float* __restrict__ kw,
                                                   const float* __restrict__ vw,
                                                   const float* __restrict__ dtb,
                                                   const float* __restrict__ Alog) {
    __shared__ __align__(16) float4 sq4[256];
    __shared__ __align__(16) float4 sk4[256];
    __shared__ float sscale[32];
    int row = blockIdx.x;
    int b = row / TT, t = row % TT;
    int tid = threadIdx.x;
    const float* base = g_qkvba + (size_t)row * NDIM1;

    // q/k: columns c..c+3
    {
        int c = tid * 4;
        float4 wq[4], wk[4];
#pragma unroll
        for (int jj = 0; jj < 4; jj++) {
            wq[jj] = *(const float4*)&qw[(c + jj) * 4];
            wk[jj] = *(const float4*)&kw[(c + jj) * 4];
        }
        float4 yq = make_float4(0.f, 0.f, 0.f, 0.f);
        float4 yk = make_float4(0.f, 0.f, 0.f, 0.f);
#pragma unroll
        for (int i = 0; i < 4; i++) {
            if (t - 3 + i >= 0) {
                const float* xr = base + (size_t)(i - 3) * NDIM1;
                float4 xq = *(const float4*)&xr[c];
                float4 xk = *(const float4*)&xr[1024 + c];
                yq.x = fmaf(xq.x, wsel(wq[0], i), yq.x);
                yq.y = fmaf(xq.y, wsel(wq[1], i), yq.y);
                yq.z = fmaf(xq.z, wsel(wq[2], i), yq.z);
                yq.w = fmaf(xq.w, wsel(wq[3], i), yq.w);
                yk.x = fmaf(xk.x, wsel(wk[0], i), yk.x);
                yk.y = fmaf(xk.y, wsel(wk[1], i), yk.y);
                yk.z = fmaf(xk.z, wsel(wk[2], i), yk.z);
                yk.w = fmaf(xk.w, wsel(wk[3], i), yk.w);
            }
        }
        sq4[tid] = silu4(yq);
        sk4[tid] = silu4(yk);
    }
    // v: two float4s per thread (2048 cols)
#pragma unroll
    for (int r = 0; r < 2; r++) {
        int c = (tid + r * 256) * 4;
        float4 wv[4];
#pragma unroll
        for (int jj = 0; jj < 4; jj++)
            wv[jj] = *(const float4*)&vw[(c + jj) * 4];
        float4 yv = make_float4(0.f, 0.f, 0.f, 0.f);
#pragma unroll
        for (int i = 0; i < 4; i++) {
            if (t - 3 + i >= 0) {
                const float* xr = base + (size_t)(i - 3) * NDIM1 + 2048;
                float4 xv = *(const float4*)&xr[c];
                yv.x = fmaf(xv.x, wsel(wv[0], i), yv.x);
                yv.y = fmaf(xv.y, wsel(wv[1], i), yv.y);
                yv.z = fmaf(xv.z, wsel(wv[2], i), yv.z);
                yv.w = fmaf(xv.w, wsel(wv[3], i), yv.w);
            }
        }
        int h = c >> 7, jc = c & 127;
        *(float4*)&g_v[(((size_t)(b * NH + h)) * TT + t) * HV + jc] = silu4(yv);
    }
    __syncthreads();
    const float* sqf = (const float*)sq4;
    const float* skf = (const float*)sk4;
    if (tid < 16) {
        float s = 0.f;
#pragma unroll
        for (int d = 0; d < 64; d++) { float x = sqf[tid * 64 + d]; s = fmaf(x, x, s); }
        sscale[tid] = rsqrtf(s + 1e-6f) * 0.125f;
    } else if (tid < 32) {
        int h = tid - 16;
        float s = 0.f;
#pragma unroll
        for (int d = 0; d < 64; d++) { float x = skf[h * 64 + d]; s = fmaf(x, x, s); }
        sscale[tid] = rsqrtf(s + 1e-6f);
    }
    if (tid < 16) {
        int h = tid;
        float bp = base[4096 + h];
        float ap = base[4112 + h];
        float beta = 1.f / (1.f + expf(-bp));
        float x = ap + dtb[h];
        float sp = (x > 20.f) ? x : log1pf(expf(x));
        float g = -expf(Alog[h]) * sp;
        size_t idx = (size_t)(b * NH + h) * TT + t;
        g_eg[idx] = expf(g);
        g_be[idx] = beta;
    }
    __syncthreads();
    {
        int c = tid * 4;
        int h = c >> 6, d = c & 63;
        size_t idx = (((size_t)(b * NH + h)) * TT + t) * DH + d;
        float sc_q = sscale[h], sc_k = sscale[16 + h];
        float4 vq = sq4[tid], vk = sk4[tid];
        vq.x *= sc_q; vq.y *= sc_q; vq.z *= sc_q; vq.w *= sc_q;
        vk.x *= sc_k; vk.y *= sc_k; vk.z *= sc_k; vk.w *= sc_k;
        *(float4*)&g_q[idx] = vq;
        *(float4*)&g_k[idx] = vk;
    }
}

// ---------------------------------------------------------------------------
// Scan (R12 math): 128 blocks = (bh, column-half), 128 threads; 2 threads per
// V-column, each owning 32 of 64 d-values. One shfl.bfly(1) per reduction.
// 16-step tiles (half the barriers of R12), cp.async double buffered.
// ---------------------------------------------------------------------------
#define ST 16   // scan tile

__global__ void __launch_bounds__(128) scan_kernel(float* __restrict__ out) {
    __shared__ __align__(16) float sk[2][ST][64];
    __shared__ __align__(16) float sq[2][ST][64];
    __shared__ __align__(16) float sv[2][ST][64];
    __shared__ __align__(16) float sg[2][ST][64];
    __shared__ __align__(16) float seb[2][2][ST];   // [buf][0=eg,1=be][tt]

    int blk = blockIdx.x;            // 0..127
    int bh = blk >> 1, cf = blk & 1; // column-half
    int b = bh >> 4, h = bh & 15;
    int j = threadIdx.x;
    int col = j >> 1, sub = j & 1;   // col 0..63 within half, sub = d-half

    const float* kp  = g_k  + (size_t)bh * TT * DH;
    const float* qp  = g_q  + (size_t)bh * TT * DH;
    const float* vp0 = g_v  + (size_t)bh * TT * HV + cf * 64;
    const float* egp = g_eg + (size_t)bh * TT;
    const float* bep = g_be + (size_t)bh * TT;
    const float* gp0 = g_gate + (size_t)b * TT * NDIM2 + h * HV + cf * 64;
    float* op        = out    + (size_t)b * TT * NDIM2 + h * HV + cf * 64 + col;

    uint32_t a_sk = smem_u32(&sk[0][0][0]);
    uint32_t a_sq = smem_u32(&sq[0][0][0]);
    uint32_t a_sv = smem_u32(&sv[0][0][0]);
    uint32_t a_sg = smem_u32(&sg[0][0][0]);
    uint32_t a_se = smem_u32(&seb[0][0][0]);

    // each array: 16 rows x 64 floats = 256 16B-chunks; 128 threads x 2
    auto issue_tile = [&](int t0, int buf) {
#pragma unroll
        for (int r = 0; r < 2; r++) {
            int id = j + r * 128;
            int row = id >> 4, seg = id & 15;
            cpa16(a_sk + buf * (ST*64*4) + row * 256 + seg * 16,
                  kp + (size_t)(t0 + row) * DH + seg * 4);
            cpa16(a_sq + buf * (ST*64*4) + row * 256 + seg * 16,
                  qp + (size_t)(t0 + row) * DH + seg * 4);
            cpa16(a_sv + buf * (ST*64*4) + row * 256 + seg * 16,
                  vp0 + (size_t)(t0 + row) * HV + seg * 4);
            cpa16(a_sg + buf * (ST*64*4) + row * 256 + seg * 16,
                  gp0 + (size_t)(t0 + row) * NDIM2 + seg * 4);
        }
        if (j < ST)            cpa4(a_se + buf * (2*ST*4) + j * 4,           egp + t0 + j);
        else if (j < 2 * ST)   cpa4(a_se + buf * (2*ST*4) + ST*4 + (j-ST)*4, bep + t0 + j - ST);
        cpa_commit();
    };

    ull S2[16];
#pragma unroll
    for (int d = 0; d < 16; d++) S2[d] = 0ULL;

    issue_tile(0, 0);
    cpa_wait0();
    __syncthreads();

    for (int t0 = 0; t0 < TT; t0 += ST) {
        int cur = (t0 >> 4) & 1;
        if (t0 + ST < TT) issue_tile(t0 + ST, cur ^ 1);

#pragma unroll 4
        for (int tt = 0; tt < ST; tt++) {
            float eg = seb[cur][0][tt], be = seb[cur][1][tt];
            float vcur = sv[cur][tt][col];
            float gcur = sg[cur][tt][col];       // already silu(gate)
            const ulonglong2* k2p = (const ulonglong2*)&sk[cur][tt][sub * 32];
            const ulonglong2* q2p = (const ulonglong2*)&sq[cur][tt][sub * 32];

            ull a0 = 0, a1 = 0, a2 = 0, a3 = 0;
#pragma unroll
            for (int i = 0; i < 4; i++) {
                ulonglong2 ka = k2p[i];
                ulonglong2 kb = k2p[i + 4];
                a0 = fma2q(ka.x, S2[2 * i],     a0);
                a1 = fma2q(ka.y, S2[2 * i + 1], a1);
                a2 = fma2q(kb.x, S2[2 * i + 8], a2);
                a3 = fma2q(kb.y, S2[2 * i + 9], a3);
            }
            float2 u0 = unpack2q(a0), u1 = unpack2q(a1), u2 = unpack2q(a2), u3 = unpack2q(a3);
            float kS_part = ((u0.x + u0.y) + (u1.x + u1.y)) + ((u2.x + u2.y) + (u3.x + u3.y));
            float kS = kS_part + shfl_bfly1(kS_part);
            float vnew = (vcur - eg * kS) * be;

            ull eg2 = pack2q(eg, eg);
            ull vn2 = pack2q(vnew, vnew);
            ull o0 = 0, o1 = 0, o2 = 0, o3 = 0;
#pragma unroll
            for (int i = 0; i < 4; i++) {
                ulonglong2 ka = k2p[i],  kb = k2p[i + 4];
                ulonglong2 qa = q2p[i],  qb = q2p[i + 4];
                S2[2 * i]     = fma2q(ka.x, vn2, mul2q(S2[2 * i],     eg2)); o0 = fma2q(qa.x, S2[2 * i],     o0);
                S2[2 * i + 1] = fma2q(ka.y, vn2, mul2q(S2[2 * i + 1], eg2)); o1 = fma2q(qa.y, S2[2 * i + 1], o1);
                S2[2 * i + 8] = fma2q(kb.x, vn2, mul2q(S2[2 * i + 8], eg2)); o2 = fma2q(qb.x, S2[2 * i + 8], o2);
                S2[2 * i + 9] = fma2q(kb.y, vn2, mul2q(S2[2 * i + 9], eg2)); o3 = fma2q(qb.y, S2[2 * i + 9], o3);
            }
            float2 w0 = unpack2q(o0), w1 = unpack2q(o1), w2 = unpack2q(o2), w3 = unpack2q(o3);
            float o_part = ((w0.x + w0.y) + (w1.x + w1.y)) + ((w2.x + w2.y) + (w3.x + w3.y));
            float o = o_part + shfl_bfly1(o_part);

            if (sub == 0)
                op[(size_t)(t0 + tt) * NDIM2] = o * gcur;
        }

        if (t0 + ST < TT) cpa_wait0();
        __syncthreads();
    }
}

// ---------------------------------------------------------------------------
extern "C" void kernel_launch(void* const* d_in, const int* in_sizes, int n_in,
                              void* d_out, int out_size) {
    const float* H    = (const float*)d_in[0];
    const float* Win  = (const float*)d_in[1];
    const float* qw   = (const float*)d_in[2];
    const float* kw   = (const float*)d_in[3];
    const float* vw   = (const float*)d_in[4];
    const float* dtb  = (const float*)d_in[5];
    const float* Alog = (const float*)d_in[6];
    const float* Wg   = (const float*)d_in[7];
    float* out = (float*)d_out;

    void *p_wt = nullptr, *p_qkvba = nullptr, *p_gate = nullptr, *p_a = nullptr;
    cudaGetSymbolAddress(&p_wt,    g_wt16);
    cudaGetSymbolAddress(&p_qkvba, g_qkvba);
    cudaGetSymbolAddress(&p_gate,  g_gate);
    cudaGetSymbolAddress(&p_a,     g_a16);
    cudaFuncSetAttribute(gemm_mma, cudaFuncAttributeMaxDynamicSharedMemorySize, GM_SMEM);

    around16_kernel<<<MM, 256>>>(H);
    transpose16_kernel<<<dim3(KK / 32, N1PAD / 32), 256>>>(Win, (__half*)p_wt, NDIM1);
    transpose16_kernel<<<dim3(KK / 32, NDIM2 / 32), 256>>>(
        Wg, (__half*)p_wt + (size_t)N1PAD * KK, NDIM2);

    gemm_mma<<<dim3(NTOT / 128, MM / 128), 128, GM_SMEM>>>(
        (const __half*)p_a, (const __half*)p_wt, (float*)p_qkvba, (float*)p_gate);

    prep_kernel<<<MM, 256>>>(qw, kw, vw, dtb, Alog);
    scan_kernel<<<2 * BB * NH, 128>>>(out);
}